// round 11
// baseline (speedup 1.0000x reference)
#include <cuda_runtime.h>
#include <cuda_bf16.h>

#define FULL_MASK 0xFFFFFFFFu

// Final: 4 lanes per row (8 bins each), 8 rows per warp.
// Phase 1: W (one 256-bit LDG) + x -> edge scan -> bin index.
// Phase 2: V loaded only by segments <= owner (cuts issue work; bytes are
// sector-bound). Owner finalizes with L1-hit reloads of (wj, vj, vj1).
__global__ __launch_bounds__(256)
void pwq_coupling_kernel(const float* __restrict__ x_b,
                         const float* __restrict__ W,
                         const float* __restrict__ V,
                         float* __restrict__ out,   // [0:n)=z, [n:2n)=log_det
                         int n)
{
    const int lane = threadIdx.x & 31;
    const int t    = lane & 3;                 // sublane within 4-lane segment
    const int warpGlobal = (blockIdx.x * blockDim.x + threadIdx.x) >> 5;
    const int row = warpGlobal * 8 + (lane >> 2);
    if (row >= n) return;                      // n % 8 == 0 -> warp-uniform

    // x first: it gates the entire compare chain.
    const float x = x_b[row];                  // 4 lanes same addr -> broadcast

    const float* __restrict__ Wrow = W + (size_t)row * 32 + t * 8;  // 32B aligned
    const float* __restrict__ Vrow = V + (size_t)row * 33 + t * 8;

    // ================= Phase 1: W only =================
    float w0, w1, w2, w3, w4, w5, w6, w7;
    asm volatile("ld.global.v8.f32 {%0,%1,%2,%3,%4,%5,%6,%7}, [%8];"
                 : "=f"(w0), "=f"(w1), "=f"(w2), "=f"(w3),
                   "=f"(w4), "=f"(w5), "=f"(w6), "=f"(w7)
                 : "l"(Wrow));

    // width prefixes
    const float pw1 = w0;
    const float pw2 = pw1 + w1;
    const float pw3 = pw2 + w2;
    const float pw4 = pw3 + w3;
    const float pw5 = pw4 + w4;
    const float pw6 = pw5 + w5;
    const float pw7 = pw6 + w6;
    const float pw8 = pw7 + w7;

    // 4-lane scan of segment width totals
    float cw = pw8;
    #pragma unroll
    for (int d = 1; d < 4; d <<= 1) {
        const float tw = __shfl_up_sync(FULL_MASK, cw, d, 4);
        if (t >= d) cw += tw;
    }
    const float bw = cw - pw8;                 // left edge of bin 8t

    // bin search: count interior edges <= val across the row
    const float val = fminf(fmaxf(x, 0.0f), 0.9999f);
    const float vb  = val - bw;                // segment-local coordinate
    int cnt = (int)(vb >= pw1) + (int)(vb >= pw2)
            + (int)(vb >= pw3) + (int)(vb >= pw4)
            + (int)(vb >= pw5) + (int)(vb >= pw6)
            + (int)(vb >= pw7) + (int)(vb >= pw8);
    cnt += __shfl_xor_sync(FULL_MASK, cnt, 1, 4);
    cnt += __shfl_xor_sync(FULL_MASK, cnt, 2, 4);
    const int bin = min(cnt, 31);
    const int seg = bin >> 3;                  // owning segment (0..3)

    // ================= Phase 2: V, segments <= seg only =================
    float pa1 = 0.f, pa2 = 0.f, pa3 = 0.f, pa4 = 0.f,
          pa5 = 0.f, pa6 = 0.f, pa7 = 0.f, pa8 = 0.f;
    if (t <= seg) {
        const float v0 = Vrow[0];
        const float v1 = Vrow[1];
        const float v2 = Vrow[2];
        const float v3 = Vrow[3];
        const float v4 = Vrow[4];
        const float v5 = Vrow[5];
        const float v6 = Vrow[6];
        const float v7 = Vrow[7];
        const float v8 = Vrow[8];              // next segment head / V[row,32]
        pa1 = 0.5f * (v0 + v1) * w0;
        pa2 = pa1 + 0.5f * (v1 + v2) * w1;
        pa3 = pa2 + 0.5f * (v2 + v3) * w2;
        pa4 = pa3 + 0.5f * (v3 + v4) * w3;
        pa5 = pa4 + 0.5f * (v4 + v5) * w4;
        pa6 = pa5 + 0.5f * (v5 + v6) * w5;
        pa7 = pa6 + 0.5f * (v6 + v7) * w6;
        pa8 = pa7 + 0.5f * (v7 + v8) * w7;
    }

    // 4-lane scan of segment area totals (skipped lanes contribute 0 — the
    // exclusive prefix at the owner only sums segments below it, all loaded).
    float ca = pa8;
    #pragma unroll
    for (int d = 1; d < 4; d <<= 1) {
        const float ta = __shfl_up_sync(FULL_MASK, ca, d, 4);
        if (t >= d) ca += ta;
    }
    const float ba = ca - pa8;                 // CDF at left edge of bin 8t

    // ================= owner lane finalizes =================
    if (t == seg) {
        const int j = bin & 7;
        // L1-hit reloads (lines fetched by this lane above).
        const float wj  = Wrow[j];
        const float vj  = Vrow[j];
        const float vj1 = Vrow[j + 1];

        const bool b1 = (j & 1), b2 = (j & 2), b4 = (j & 4);
        const float pwj = b4 ? (b2 ? (b1 ? pw7 : pw6) : (b1 ? pw5 : pw4))
                             : (b2 ? (b1 ? pw3 : pw2) : (b1 ? pw1 : 0.0f));
        const float paj = b4 ? (b2 ? (b1 ? pa7 : pa6) : (b1 ? pa5 : pa4))
                             : (b2 ? (b1 ? pa3 : pa2) : (b1 ? pa1 : 0.0f));

        const float alpha = __fdividef(val - (bw + pwj), wj + 1e-8f);
        const float dv    = vj1 - vj;
        out[row]     = (ba + paj) + alpha * wj * (vj + 0.5f * alpha * dv);
        out[n + row] = __logf(vj + alpha * dv + 1e-8f);
    }
}

extern "C" void kernel_launch(void* const* d_in, const int* in_sizes, int n_in,
                              void* d_out, int out_size)
{
    const float* x_b = (const float*)d_in[0];
    const float* W   = (const float*)d_in[1];
    const float* V   = (const float*)d_in[2];
    float* out = (float*)d_out;

    const int n = in_sizes[0];
    const int rowsPerBlock = 64;               // 8 warps * 8 rows
    const int blocks = (n + rowsPerBlock - 1) / rowsPerBlock;
    pwq_coupling_kernel<<<blocks, 256>>>(x_b, W, V, out, n);
}

// round 12
// speedup vs baseline: 1.0753x; 1.0753x over previous
#include <cuda_runtime.h>
#include <cuda_bf16.h>

#define FULL_MASK 0xFFFFFFFFu

// 4 lanes per row (8 bins each), 8 rows per warp.
// Phase 1: W-only (v8f32 load) -> edges scan -> bin index.
// Phase 2: only segments <= owner load V (saves ~37% of V issue work).
__global__ __launch_bounds__(256)
void pwq_coupling_kernel(const float* __restrict__ x_b,
                         const float* __restrict__ W,
                         const float* __restrict__ V,
                         float* __restrict__ out,   // [0:n)=z, [n:2n)=log_det
                         int n)
{
    const int lane = threadIdx.x & 31;
    const int t    = lane & 3;                 // sublane within 4-lane segment
    const int warpGlobal = (blockIdx.x * blockDim.x + threadIdx.x) >> 5;
    const int row = warpGlobal * 8 + (lane >> 2);
    if (row >= n) return;                      // n % 8 == 0 -> warp-uniform

    const float* __restrict__ Wrow = W + (size_t)row * 32 + t * 8;  // 32B aligned
    const float* __restrict__ Vrow = V + (size_t)row * 33 + t * 8;

    // ================= Phase 1: W + x only =================
    float w0, w1, w2, w3, w4, w5, w6, w7;
    asm volatile("ld.global.v8.f32 {%0,%1,%2,%3,%4,%5,%6,%7}, [%8];"
                 : "=f"(w0), "=f"(w1), "=f"(w2), "=f"(w3),
                   "=f"(w4), "=f"(w5), "=f"(w6), "=f"(w7)
                 : "l"(Wrow));
    const float x = x_b[row];                  // 4 lanes same addr -> broadcast

    // width prefixes
    const float pw1 = w0;
    const float pw2 = pw1 + w1;
    const float pw3 = pw2 + w2;
    const float pw4 = pw3 + w3;
    const float pw5 = pw4 + w4;
    const float pw6 = pw5 + w5;
    const float pw7 = pw6 + w6;
    const float pw8 = pw7 + w7;

    // 4-lane scan of segment width totals
    float cw = pw8;
    #pragma unroll
    for (int d = 1; d < 4; d <<= 1) {
        const float tw = __shfl_up_sync(FULL_MASK, cw, d, 4);
        if (t >= d) cw += tw;
    }
    const float bw = cw - pw8;                 // left edge of bin 8t

    // bin search: count interior edges <= val across the row
    const float val = fminf(fmaxf(x, 0.0f), 0.9999f);
    const float vb  = val - bw;                // segment-local coordinate
    int cnt = (int)(vb >= pw1) + (int)(vb >= pw2)
            + (int)(vb >= pw3) + (int)(vb >= pw4)
            + (int)(vb >= pw5) + (int)(vb >= pw6)
            + (int)(vb >= pw7) + (int)(vb >= pw8);
    cnt += __shfl_xor_sync(FULL_MASK, cnt, 1, 4);
    cnt += __shfl_xor_sync(FULL_MASK, cnt, 2, 4);
    const int bin = min(cnt, 31);
    const int seg = bin >> 3;                  // owning segment (0..3)

    // ================= Phase 2: V, only segments <= seg =================
    float v0 = 0.f, v1 = 0.f, v2 = 0.f, v3 = 0.f,
          v4 = 0.f, v5 = 0.f, v6 = 0.f, v7 = 0.f, v8 = 0.f;
    if (t <= seg) {
        v0 = Vrow[0];
        v1 = Vrow[1];
        v2 = Vrow[2];
        v3 = Vrow[3];
        v4 = Vrow[4];
        v5 = Vrow[5];
        v6 = Vrow[6];
        v7 = Vrow[7];
        v8 = Vrow[8];                          // first elem of next segment / V[row,32]
    }

    // area prefixes (zero for skipped segments)
    const float pa1 = 0.5f * (v0 + v1) * w0;
    const float pa2 = pa1 + 0.5f * (v1 + v2) * w1;
    const float pa3 = pa2 + 0.5f * (v2 + v3) * w2;
    const float pa4 = pa3 + 0.5f * (v3 + v4) * w3;
    const float pa5 = pa4 + 0.5f * (v4 + v5) * w4;
    const float pa6 = pa5 + 0.5f * (v5 + v6) * w5;
    const float pa7 = pa6 + 0.5f * (v6 + v7) * w6;
    const float pa8 = pa7 + 0.5f * (v7 + v8) * w7;

    // 4-lane scan of segment area totals (skipped lanes contribute 0,
    // which is correct for the exclusive prefix at the owner).
    float ca = pa8;
    #pragma unroll
    for (int d = 1; d < 4; d <<= 1) {
        const float ta = __shfl_up_sync(FULL_MASK, ca, d, 4);
        if (t >= d) ca += ta;
    }
    const float ba = ca - pa8;                 // CDF at left edge of bin 8t

    // ================= owner lane finalizes =================
    if (t == seg) {
        const int j = bin & 7;
        // L1-hit reloads (lines fetched in phase 2 by this lane).
        const float wj  = Wrow[j];
        const float vj  = Vrow[j];
        const float vj1 = Vrow[j + 1];

        const bool b1 = (j & 1), b2 = (j & 2), b4 = (j & 4);
        const float pwj = b4 ? (b2 ? (b1 ? pw7 : pw6) : (b1 ? pw5 : pw4))
                             : (b2 ? (b1 ? pw3 : pw2) : (b1 ? pw1 : 0.0f));
        const float paj = b4 ? (b2 ? (b1 ? pa7 : pa6) : (b1 ? pa5 : pa4))
                             : (b2 ? (b1 ? pa3 : pa2) : (b1 ? pa1 : 0.0f));

        const float alpha = __fdividef(val - (bw + pwj), wj + 1e-8f);
        const float dv    = vj1 - vj;
        out[row]     = (ba + paj) + alpha * wj * (vj + 0.5f * alpha * dv);
        out[n + row] = __logf(vj + alpha * dv + 1e-8f);
    }
}

extern "C" void kernel_launch(void* const* d_in, const int* in_sizes, int n_in,
                              void* d_out, int out_size)
{
    const float* x_b = (const float*)d_in[0];
    const float* W   = (const float*)d_in[1];
    const float* V   = (const float*)d_in[2];
    float* out = (float*)d_out;

    const int n = in_sizes[0];
    const int rowsPerBlock = 64;               // 8 warps * 8 rows
    const int blocks = (n + rowsPerBlock - 1) / rowsPerBlock;
    pwq_coupling_kernel<<<blocks, 256>>>(x_b, W, V, out, n);
}